// round 14
// baseline (speedup 1.0000x reference)
#include <cuda_runtime.h>
#include <cuda_bf16.h>
#include <cstdint>

#define B_     32
#define S_     2048
#define D_     1536
#define G_     150
#define K_     9
#define R_     32
#define MAXT   150
#define LW     48
#define NT     416        // 384 consumers + 1 producer warp
#define NCONS  384
#define PPB    15         // groups per block
#define CHUNKS 10
#define ROWB   6144       // bytes per hidden row
#define TRIOR  3          // rows per ring slot
#define TRIOB  (TRIOR*ROWB)
#define SLOTS  2          // ring depth (2 x 18KB)
#define NJ     (PPB*K_)   // 135 rows per block
#define NTRIOS (NJ/TRIOR) // 45

__device__ __forceinline__ uint32_t smem_u32(const void* p) {
    uint32_t a;
    asm("{ .reg .u64 t; cvta.to.shared.u64 t, %1; cvt.u32.u64 %0, t; }" : "=r"(a) : "l"(p));
    return a;
}
__device__ __forceinline__ void mbar_wait_acq(uint32_t mbar, uint32_t parity) {
    asm volatile(
        "{\n\t.reg .pred P;\n\tW%=:\n\t"
        "mbarrier.try_wait.parity.acquire.cta.shared::cta.b64 P, [%0], %1, 0x989680;\n\t"
        "@P bra.uni D%=;\n\tbra.uni W%=;\n\tD%=:\n\t}"
        :: "r"(mbar), "r"(parity) : "memory");
}
__device__ __forceinline__ void mbar_wait_rlx(uint32_t mbar, uint32_t parity) {
    asm volatile(
        "{\n\t.reg .pred P;\n\tW%=:\n\t"
        "mbarrier.try_wait.parity.relaxed.cta.shared::cta.b64 P, [%0], %1, 0x989680;\n\t"
        "@P bra.uni D%=;\n\tbra.uni W%=;\n\tD%=:\n\t}"
        :: "r"(mbar), "r"(parity) : "memory");
}
#define BAR_SYNC(id, n)   asm volatile("bar.sync %0, %1;"   :: "r"(id), "r"(n) : "memory")
#define BAR_ARRIVE(id, n) asm volatile("bar.arrive %0, %1;" :: "r"(id), "r"(n) : "memory")

// ---------------------------------------------------------------------------
// Group-centric warp-specialized gather-average. 320 blocks x 135 rows
// (10 chunks x 32 samples): minimal prep replication, max payload per
// pipeline ramp. Producer warp holds 5 gather pointers/lane in registers,
// publishes mbarrier init via non-blocking bar.arrive, and streams rows
// through a 2 x 18KB smem ring via cp.async.bulk. Consumers run prep
// (removal bitmap, counts, keep-scan -> dest permutation + 1/cnt) fully
// underneath the in-flight loads.
// ---------------------------------------------------------------------------
__global__ __launch_bounds__(NT, 3)
void fused_pool_gc(const float* __restrict__ h,
                   const int* __restrict__ patch_range,
                   const int* __restrict__ patch_idx,
                   const int* __restrict__ remove_idx,
                   float* __restrict__ out,
                   float* __restrict__ attn_out)
{
    const int c = blockIdx.x;         // group chunk 0..9
    const int b = blockIdx.y;         // sample
    const int t = threadIdx.x;        // 0..415
    const int g0 = c * PPB;

    __shared__ __align__(128) char s_slots[SLOTS * TRIOB];   // 36864 B
    __shared__ __align__(8) unsigned long long s_full[SLOTS];
    __shared__ __align__(8) unsigned long long s_empty[SLOTS];
    __shared__ float s_inv[PPB];
    __shared__ int s_dest[PPB];
    __shared__ unsigned s_bm[LW];
    __shared__ int s_cnt[G_];
    __shared__ unsigned s_kw[5];
    __shared__ int s_wp[5];

    const uint32_t slot0   = smem_u32(s_slots);
    const uint32_t fullb0  = smem_u32(s_full);
    const uint32_t emptyb0 = smem_u32(s_empty);

    if (t >= NCONS) {
        // ================= producer warp ===================================
        const int q = t - NCONS;      // lane 0..31
        if (q == 0) {
#pragma unroll
            for (int s = 0; s < SLOTS; s++) {
                asm volatile("mbarrier.init.shared.b64 [%0], %1;" :: "r"(fullb0 + 8u*s),  "r"(1u)  : "memory");
                asm volatile("mbarrier.init.shared.b64 [%0], %1;" :: "r"(emptyb0 + 8u*s), "r"(12u) : "memory");
            }
            asm volatile("fence.proxy.async.shared::cta;" ::: "memory");
        }
        __syncwarp();
        BAR_ARRIVE(0, NT);            // publish init; do NOT wait for consumers

        // 5 gather pointers per lane, in registers: rows q, q+32, ..., q+128
        const int start = patch_range[b * 2 + 0];
        const int end   = patch_range[b * 2 + 1];
        const float* pr[5];
#pragma unroll
        for (int r = 0; r < 5; r++) {
            pr[r] = h;                // dummy, never issued for j >= NJ
            int j = q + r * 32;
            if (j < NJ) {
                int g = g0 + j / K_, k = j % K_;
                int v = patch_idx[(b * G_ + g) * K_ + k];
                int row = (v >= 0) ? (start + v) : (end + 1 + v);   // ref wrap
                pr[r] = h + ((size_t)b * S_ + row) * (size_t)D_;
            }
        }
        __syncwarp();

#pragma unroll 1
        for (int tr = 0; tr < NTRIOS; tr++) {
            int s = tr & 1, u = tr >> 1;
            uint32_t fb = fullb0 + 8u * s;
            if (u > 0) mbar_wait_rlx(emptyb0 + 8u * s, (unsigned)((u - 1) & 1));
            if (q == 0)
                asm volatile("mbarrier.arrive.expect_tx.shared.b64 _, [%0], %1;"
                             :: "r"(fb), "r"((unsigned)TRIOB) : "memory");
            __syncwarp();
            int j0 = tr * TRIOR;
#pragma unroll
            for (int r3 = 0; r3 < TRIOR; r3++) {
                int j = j0 + r3;
                if (q == (j & 31)) {
                    const float* p = pr[j >> 5];
                    asm volatile(
                        "cp.async.bulk.shared::cta.global.mbarrier::complete_tx::bytes [%0], [%1], %2, [%3];"
                        :: "r"(slot0 + (unsigned)(s * TRIOB + r3 * ROWB)),
                           "l"(p), "r"((unsigned)ROWB), "r"(fb) : "memory");
                }
            }
        }
        return;
    }

    // ================= consumers (0..383): prep under flying loads =========
    BAR_SYNC(0, NT);                  // wait for mbarrier init
    if (t < LW) s_bm[t] = 0u;
    BAR_SYNC(1, NCONS);
    if (t < R_) {
        int v = remove_idx[b * R_ + t];
        if ((unsigned)v < 1536u) atomicOr(&s_bm[v >> 5], 1u << (v & 31));
    }
    BAR_SYNC(1, NCONS);

    int keep = 0;
    if (t < G_) {
        const int* gi = patch_idx + (b * G_ + t) * K_;
        int cnt = 0;
#pragma unroll
        for (int k = 0; k < K_; k++) {
            int v = gi[k];
            bool valid = (v != -1);
            if (valid && (unsigned)v < 1536u)
                valid = ((s_bm[v >> 5] >> (v & 31)) & 1u) == 0u;
            cnt += valid ? 1 : 0;
        }
        s_cnt[t] = cnt;
        keep = (cnt > 0) ? 1 : 0;
    }
    const unsigned bmask = __ballot_sync(0xFFFFFFFFu, keep);
    const int w = t >> 5, lane = t & 31;
    if (lane == 0 && w < 5) s_kw[w] = bmask;
    BAR_SYNC(1, NCONS);
    if (t < 5) s_wp[t] = __popc(s_kw[t]);
    BAR_SYNC(1, NCONS);

    if (t < PPB) {
        int g = g0 + t;
        int nk = s_wp[0] + s_wp[1] + s_wp[2] + s_wp[3] + s_wp[4];
        int wi = g >> 5;
        int rk = __popc(s_kw[wi] & ((1u << (g & 31)) - 1u));
        for (int w2 = 0; w2 < wi; w2++) rk += s_wp[w2];
        int kp = (s_kw[wi] >> (g & 31)) & 1u;
        int dest = kp ? (MAXT - nk + rk) : (g - rk);   // permutation of 0..149
        s_dest[t] = dest;
        s_inv[t]  = kp ? 1.0f / (float)max(s_cnt[g], 1) : 0.0f;
        attn_out[b * MAXT + dest] = kp ? 1.0f : 0.0f;
    }
    BAR_SYNC(1, NCONS);

    // ================= consume: 15 groups x 3 trios ========================
    float* osample = out + (size_t)b * MAXT * D_;
#pragma unroll 1
    for (int i = 0; i < PPB; i++) {
        float4 acc = make_float4(0.f, 0.f, 0.f, 0.f);
#pragma unroll 1
        for (int t3 = 0; t3 < 3; t3++) {
            int tr = i * 3 + t3;
            int s = tr & 1, u = tr >> 1;
            mbar_wait_acq(fullb0 + 8u * s, (unsigned)(u & 1));
            const float4* p = reinterpret_cast<const float4*>(s_slots + s * TRIOB);
#pragma unroll
            for (int r = 0; r < TRIOR; r++) {
                float4 v = p[r * (ROWB / 16) + t];
                acc.x += v.x; acc.y += v.y; acc.z += v.z; acc.w += v.w;
            }
            __syncwarp();
            if (lane == 0)
                asm volatile("mbarrier.arrive.shared.b64 _, [%0];"
                             :: "r"(emptyb0 + 8u * s) : "memory");
        }
        const float inv = s_inv[i];
        acc.x *= inv; acc.y *= inv; acc.z *= inv; acc.w *= inv;
        reinterpret_cast<float4*>(osample + (size_t)s_dest[i] * D_)[t] = acc;
    }
}

extern "C" void kernel_launch(void* const* d_in, const int* in_sizes, int n_in,
                              void* d_out, int out_size)
{
    const float* hidden    = (const float*)d_in[0];  // [B,S,D] f32
    // d_in[1] attention_mask, d_in[2] image_grid_thw: unused by the math
    const int* patch_range = (const int*)d_in[3];    // [B,2]
    const int* patch_idx   = (const int*)d_in[4];    // [B,G,K]
    const int* remove_idx  = (const int*)d_in[5];    // [B,R]

    float* out      = (float*)d_out;                 // [B,MAXT,D]
    float* attn_out = out + (size_t)B_ * MAXT * D_;  // [B,MAXT]

    dim3 grid(CHUNKS, B_);
    fused_pool_gc<<<grid, NT>>>(hidden, patch_range, patch_idx, remove_idx,
                                out, attn_out);
}

// round 16
// speedup vs baseline: 1.1635x; 1.1635x over previous
#include <cuda_runtime.h>
#include <cuda_bf16.h>
#include <cstdint>

#define B_     32
#define S_     2048
#define D_     1536
#define G_     150
#define K_     9
#define R_     32
#define MAXT   150
#define LW     48
#define NT     416        // 384 consumers + 1 producer warp
#define NCONS  384
#define PPB    10         // groups per block
#define CHUNKS 15
#define ROWB   6144       // bytes per hidden row
#define TRIOR  3          // rows per ring slot
#define TRIOB  (TRIOR*ROWB)
#define SLOTS  2          // ring depth (2 x 18KB)
#define NJ     (PPB*K_)   // 90 rows per block
#define NTRIOS (NJ/TRIOR) // 30

__device__ __forceinline__ uint32_t smem_u32(const void* p) {
    uint32_t a;
    asm("{ .reg .u64 t; cvta.to.shared.u64 t, %1; cvt.u32.u64 %0, t; }" : "=r"(a) : "l"(p));
    return a;
}
__device__ __forceinline__ void mbar_wait_acq(uint32_t mbar, uint32_t parity) {
    asm volatile(
        "{\n\t.reg .pred P;\n\tW%=:\n\t"
        "mbarrier.try_wait.parity.acquire.cta.shared::cta.b64 P, [%0], %1, 0x989680;\n\t"
        "@P bra.uni D%=;\n\tbra.uni W%=;\n\tD%=:\n\t}"
        :: "r"(mbar), "r"(parity) : "memory");
}
__device__ __forceinline__ void mbar_wait_rlx(uint32_t mbar, uint32_t parity) {
    asm volatile(
        "{\n\t.reg .pred P;\n\tW%=:\n\t"
        "mbarrier.try_wait.parity.relaxed.cta.shared::cta.b64 P, [%0], %1, 0x989680;\n\t"
        "@P bra.uni D%=;\n\tbra.uni W%=;\n\tD%=:\n\t}"
        :: "r"(mbar), "r"(parity) : "memory");
}
#define BAR_SYNC(id, n)   asm volatile("bar.sync %0, %1;"   :: "r"(id), "r"(n) : "memory")
#define BAR_ARRIVE(id, n) asm volatile("bar.arrive %0, %1;" :: "r"(id), "r"(n) : "memory")

// ---------------------------------------------------------------------------
// Group-centric warp-specialized gather-average (best-measured config:
// 480 blocks x 90 rows, 2 x 18KB ring, 4 blocks/SM). Producer warp holds
// gather pointers in registers (3/lane), publishes mbarrier init via
// non-blocking bar.arrive, and issues cp.async.bulk per-lane. Consumers run
// prep (removal bitmap, counts, keep-scan -> dest permutation + 1/cnt)
// underneath the in-flight loads, then accumulate trios from the smem ring.
// ---------------------------------------------------------------------------
__global__ __launch_bounds__(NT, 4)
void fused_pool_gc(const float* __restrict__ h,
                   const int* __restrict__ patch_range,
                   const int* __restrict__ patch_idx,
                   const int* __restrict__ remove_idx,
                   float* __restrict__ out,
                   float* __restrict__ attn_out)
{
    const int c = blockIdx.x;         // group chunk 0..14
    const int b = blockIdx.y;         // sample
    const int t = threadIdx.x;        // 0..415
    const int g0 = c * PPB;

    __shared__ __align__(128) char s_slots[SLOTS * TRIOB];   // 36864 B
    __shared__ __align__(8) unsigned long long s_full[SLOTS];
    __shared__ __align__(8) unsigned long long s_empty[SLOTS];
    __shared__ float s_inv[PPB];
    __shared__ int s_dest[PPB];
    __shared__ unsigned s_bm[LW];
    __shared__ int s_cnt[G_];
    __shared__ unsigned s_kw[5];
    __shared__ int s_wp[5];

    const uint32_t slot0   = smem_u32(s_slots);
    const uint32_t fullb0  = smem_u32(s_full);
    const uint32_t emptyb0 = smem_u32(s_empty);

    if (t >= NCONS) {
        // ================= producer warp ===================================
        const int q = t - NCONS;      // lane 0..31
        if (q == 0) {
#pragma unroll
            for (int s = 0; s < SLOTS; s++) {
                asm volatile("mbarrier.init.shared.b64 [%0], %1;" :: "r"(fullb0 + 8u*s),  "r"(1u)  : "memory");
                asm volatile("mbarrier.init.shared.b64 [%0], %1;" :: "r"(emptyb0 + 8u*s), "r"(12u) : "memory");
            }
            asm volatile("fence.proxy.async.shared::cta;" ::: "memory");
        }
        __syncwarp();
        BAR_ARRIVE(0, NT);            // publish init; do NOT wait for consumers

        // 3 gather pointers per lane, in registers: rows q, q+32, q+64
        const int start = patch_range[b * 2 + 0];
        const int end   = patch_range[b * 2 + 1];
        const float* p0 = 0; const float* p1 = 0; const float* p2 = 0;
#pragma unroll
        for (int r = 0; r < 3; r++) {
            int j = q + r * 32;
            if (j < NJ) {
                int g = g0 + j / K_, k = j % K_;
                int v = patch_idx[(b * G_ + g) * K_ + k];
                int row = (v >= 0) ? (start + v) : (end + 1 + v);   // ref wrap
                const float* p = h + ((size_t)b * S_ + row) * (size_t)D_;
                if (r == 0) p0 = p; else if (r == 1) p1 = p; else p2 = p;
            }
        }
        __syncwarp();

#pragma unroll 1
        for (int tr = 0; tr < NTRIOS; tr++) {
            int s = tr & 1, u = tr >> 1;
            uint32_t fb = fullb0 + 8u * s;
            if (u > 0) mbar_wait_rlx(emptyb0 + 8u * s, (unsigned)((u - 1) & 1));
            if (q == 0)
                asm volatile("mbarrier.arrive.expect_tx.shared.b64 _, [%0], %1;"
                             :: "r"(fb), "r"((unsigned)TRIOB) : "memory");
            __syncwarp();
            int j0 = tr * TRIOR;
#pragma unroll
            for (int r3 = 0; r3 < TRIOR; r3++) {
                int j = j0 + r3;
                if (q == (j & 31)) {
                    int hi = j >> 5;
                    const float* p = (hi == 0) ? p0 : ((hi == 1) ? p1 : p2);
                    asm volatile(
                        "cp.async.bulk.shared::cta.global.mbarrier::complete_tx::bytes [%0], [%1], %2, [%3];"
                        :: "r"(slot0 + (unsigned)(s * TRIOB + r3 * ROWB)),
                           "l"(p), "r"((unsigned)ROWB), "r"(fb) : "memory");
                }
            }
        }
        return;
    }

    // ================= consumers (0..383): prep under flying loads =========
    BAR_SYNC(0, NT);                  // wait for mbarrier init
    if (t < LW) s_bm[t] = 0u;
    BAR_SYNC(1, NCONS);
    if (t < R_) {
        int v = remove_idx[b * R_ + t];
        if ((unsigned)v < 1536u) atomicOr(&s_bm[v >> 5], 1u << (v & 31));
    }
    BAR_SYNC(1, NCONS);

    int keep = 0;
    if (t < G_) {
        const int* gi = patch_idx + (b * G_ + t) * K_;
        int cnt = 0;
#pragma unroll
        for (int k = 0; k < K_; k++) {
            int v = gi[k];
            bool valid = (v != -1);
            if (valid && (unsigned)v < 1536u)
                valid = ((s_bm[v >> 5] >> (v & 31)) & 1u) == 0u;
            cnt += valid ? 1 : 0;
        }
        s_cnt[t] = cnt;
        keep = (cnt > 0) ? 1 : 0;
    }
    const unsigned bmask = __ballot_sync(0xFFFFFFFFu, keep);
    const int w = t >> 5, lane = t & 31;
    if (lane == 0 && w < 5) s_kw[w] = bmask;
    BAR_SYNC(1, NCONS);
    if (t < 5) s_wp[t] = __popc(s_kw[t]);
    BAR_SYNC(1, NCONS);

    if (t < PPB) {
        int g = g0 + t;
        int nk = s_wp[0] + s_wp[1] + s_wp[2] + s_wp[3] + s_wp[4];
        int wi = g >> 5;
        int rk = __popc(s_kw[wi] & ((1u << (g & 31)) - 1u));
        for (int w2 = 0; w2 < wi; w2++) rk += s_wp[w2];
        int kp = (s_kw[wi] >> (g & 31)) & 1u;
        int dest = kp ? (MAXT - nk + rk) : (g - rk);   // permutation of 0..149
        s_dest[t] = dest;
        s_inv[t]  = kp ? 1.0f / (float)max(s_cnt[g], 1) : 0.0f;
        attn_out[b * MAXT + dest] = kp ? 1.0f : 0.0f;
    }
    BAR_SYNC(1, NCONS);

    // ================= consume: 10 groups x 3 trios ========================
    float* osample = out + (size_t)b * MAXT * D_;
#pragma unroll 1
    for (int i = 0; i < PPB; i++) {
        float4 acc = make_float4(0.f, 0.f, 0.f, 0.f);
#pragma unroll 1
        for (int t3 = 0; t3 < 3; t3++) {
            int tr = i * 3 + t3;
            int s = tr & 1, u = tr >> 1;
            mbar_wait_acq(fullb0 + 8u * s, (unsigned)(u & 1));
            const float4* p = reinterpret_cast<const float4*>(s_slots + s * TRIOB);
#pragma unroll
            for (int r = 0; r < TRIOR; r++) {
                float4 v = p[r * (ROWB / 16) + t];
                acc.x += v.x; acc.y += v.y; acc.z += v.z; acc.w += v.w;
            }
            __syncwarp();
            if (lane == 0)
                asm volatile("mbarrier.arrive.shared.b64 _, [%0];"
                             :: "r"(emptyb0 + 8u * s) : "memory");
        }
        const float inv = s_inv[i];
        acc.x *= inv; acc.y *= inv; acc.z *= inv; acc.w *= inv;
        reinterpret_cast<float4*>(osample + (size_t)s_dest[i] * D_)[t] = acc;
    }
}

extern "C" void kernel_launch(void* const* d_in, const int* in_sizes, int n_in,
                              void* d_out, int out_size)
{
    const float* hidden    = (const float*)d_in[0];  // [B,S,D] f32
    // d_in[1] attention_mask, d_in[2] image_grid_thw: unused by the math
    const int* patch_range = (const int*)d_in[3];    // [B,2]
    const int* patch_idx   = (const int*)d_in[4];    // [B,G,K]
    const int* remove_idx  = (const int*)d_in[5];    // [B,R]

    float* out      = (float*)d_out;                 // [B,MAXT,D]
    float* attn_out = out + (size_t)B_ * MAXT * D_;  // [B,MAXT]

    dim3 grid(CHUNKS, B_);
    fused_pool_gc<<<grid, NT>>>(hidden, patch_range, patch_idx, remove_idx,
                                out, attn_out);
}